// round 1
// baseline (speedup 1.0000x reference)
#include <cuda_runtime.h>

#define NH   12
#define HD   64
#define NSEQ 2048
#define NB   2
#define DIN  768
#define PAD  68   // row stride in floats for attention smem tiles (bank-conflict pad)

// scratch: h = x @ Wq^T, laid out [b][head][q][d]  (q,k,v are all this tensor)
__device__ float g_h[NB * NH * NSEQ * HD];

// ---------------------------------------------------------------------------
// Kernel 1: qkv projection GEMM  y[m][n] = sum_k x[m][k] * Wq[n][k]
// scattered into g_h[((b*NH+head)*NSEQ + q)*HD + d]
// grid (64, 12), block 256, 64x64 block tile, BK=32
// ---------------------------------------------------------------------------
__global__ __launch_bounds__(256) void qkv_gemm(const float* __restrict__ x,
                                                const float* __restrict__ Wq) {
    __shared__ float As[64][36];
    __shared__ float Bs[64][36];
    const int tid = threadIdx.x;
    const int tx = tid & 15, ty = tid >> 4;
    const int m0 = blockIdx.x * 64;
    const int head = blockIdx.y;
    const int n0 = head * 64;

    float acc[4][4] = {};

    for (int k0 = 0; k0 < DIN; k0 += 32) {
        #pragma unroll
        for (int i = 0; i < 2; ++i) {
            int lin = tid + i * 256;           // float4 index, 512 per tile
            int row = lin >> 3, c4 = (lin & 7) * 4;
            float4 av = *(const float4*)&x [(m0 + row) * DIN + k0 + c4];
            float4 bv = *(const float4*)&Wq[(n0 + row) * DIN + k0 + c4];
            *(float4*)&As[row][c4] = av;
            *(float4*)&Bs[row][c4] = bv;
        }
        __syncthreads();
        #pragma unroll
        for (int k4 = 0; k4 < 8; ++k4) {
            float4 a4[4], b4[4];
            #pragma unroll
            for (int r = 0; r < 4; ++r) a4[r] = *(float4*)&As[ty * 4 + r][k4 * 4];
            #pragma unroll
            for (int c = 0; c < 4; ++c) b4[c] = *(float4*)&Bs[tx + 16 * c][k4 * 4];
            #pragma unroll
            for (int r = 0; r < 4; ++r)
                #pragma unroll
                for (int c = 0; c < 4; ++c)
                    acc[r][c] += a4[r].x * b4[c].x + a4[r].y * b4[c].y +
                                 a4[r].z * b4[c].z + a4[r].w * b4[c].w;
        }
        __syncthreads();
    }

    #pragma unroll
    for (int r = 0; r < 4; ++r) {
        int m = m0 + ty * 4 + r;
        int b = m >> 11, q = m & 2047;
        float* dst = &g_h[((size_t)(b * NH + head) * NSEQ + q) * HD];
        #pragma unroll
        for (int c = 0; c < 4; ++c)
            dst[tx + 16 * c] = acc[r][c];
    }
}

// ---------------------------------------------------------------------------
// Kernel 2: fused causal flash attention, K tile == V tile (shared weights).
// grid (32 q-tiles, 24 bh), block 256. Output layout out[bh][d][q].
// ---------------------------------------------------------------------------
__global__ __launch_bounds__(256) void attn_kernel(float* __restrict__ out) {
    extern __shared__ float smem[];
    float* Qs = smem;                 // 64*PAD
    float* Ks = smem + 64 * PAD;      // 64*PAD  (serves as both K and V)
    float* Ps = smem + 2 * 64 * PAD;  // 64*PAD

    const int tid = threadIdx.x;
    const int tx = tid & 15, ty = tid >> 4;
    const int qt = blockIdx.x;        // query tile 0..31
    const int bh = blockIdx.y;        // 0..23
    const float* hbase = &g_h[(size_t)bh * NSEQ * HD];
    const int q0 = qt * 64;

    // load Q tile [64][64]
    #pragma unroll
    for (int i = 0; i < 4; ++i) {
        int lin = tid + i * 256;           // float4 idx, 1024 total
        int row = lin >> 4, c4 = (lin & 15) * 4;
        *(float4*)&Qs[row * PAD + c4] = *(const float4*)&hbase[(q0 + row) * HD + c4];
    }

    float acc[4][4] = {};
    float mrow[4], lrow[4];
    #pragma unroll
    for (int r = 0; r < 4; ++r) { mrow[r] = -1e30f; lrow[r] = 0.f; }

    for (int kt = 0; kt <= qt; ++kt) {
        __syncthreads();  // Ks/Ps from prev iter no longer in use; Qs visible (iter 0)
        #pragma unroll
        for (int i = 0; i < 4; ++i) {
            int lin = tid + i * 256;
            int row = lin >> 4, c4 = (lin & 15) * 4;
            *(float4*)&Ks[row * PAD + c4] =
                *(const float4*)&hbase[(kt * 64 + row) * HD + c4];
        }
        __syncthreads();

        // ---- S = Q K^T  (thread rows ty*4+r, key cols tx+16*c) ----
        float s[4][4] = {};
        #pragma unroll
        for (int k4 = 0; k4 < 16; ++k4) {
            float4 qv[4], kv[4];
            #pragma unroll
            for (int r = 0; r < 4; ++r) qv[r] = *(float4*)&Qs[(ty * 4 + r) * PAD + k4 * 4];
            #pragma unroll
            for (int c = 0; c < 4; ++c) kv[c] = *(float4*)&Ks[(tx + 16 * c) * PAD + k4 * 4];
            #pragma unroll
            for (int r = 0; r < 4; ++r)
                #pragma unroll
                for (int c = 0; c < 4; ++c)
                    s[r][c] += qv[r].x * kv[c].x + qv[r].y * kv[c].y +
                               qv[r].z * kv[c].z + qv[r].w * kv[c].w;
        }

        // scale + causal mask (only diagonal tile needs masking)
        if (kt == qt) {
            #pragma unroll
            for (int r = 0; r < 4; ++r) {
                int qq = ty * 4 + r;
                #pragma unroll
                for (int c = 0; c < 4; ++c) {
                    int kk = tx + 16 * c;
                    s[r][c] = (kk > qq) ? -1e30f : s[r][c] * 0.125f;
                }
            }
        } else {
            #pragma unroll
            for (int r = 0; r < 4; ++r)
                #pragma unroll
                for (int c = 0; c < 4; ++c) s[r][c] *= 0.125f;
        }

        // ---- online softmax (rows split across 16 tx lanes) ----
        #pragma unroll
        for (int r = 0; r < 4; ++r) {
            float mx = fmaxf(fmaxf(s[r][0], s[r][1]), fmaxf(s[r][2], s[r][3]));
            mx = fmaxf(mx, __shfl_xor_sync(0xffffffffu, mx, 1));
            mx = fmaxf(mx, __shfl_xor_sync(0xffffffffu, mx, 2));
            mx = fmaxf(mx, __shfl_xor_sync(0xffffffffu, mx, 4));
            mx = fmaxf(mx, __shfl_xor_sync(0xffffffffu, mx, 8));
            float newm = fmaxf(mrow[r], mx);
            float corr = __expf(mrow[r] - newm);
            mrow[r] = newm;
            float rs = 0.f;
            #pragma unroll
            for (int c = 0; c < 4; ++c) {
                float p = __expf(s[r][c] - newm);
                s[r][c] = p;
                rs += p;
            }
            rs += __shfl_xor_sync(0xffffffffu, rs, 1);
            rs += __shfl_xor_sync(0xffffffffu, rs, 2);
            rs += __shfl_xor_sync(0xffffffffu, rs, 4);
            rs += __shfl_xor_sync(0xffffffffu, rs, 8);
            lrow[r] = lrow[r] * corr + rs;
            #pragma unroll
            for (int c = 0; c < 4; ++c) acc[r][c] *= corr;
        }

        // stage P to smem
        #pragma unroll
        for (int r = 0; r < 4; ++r)
            #pragma unroll
            for (int c = 0; c < 4; ++c)
                Ps[(ty * 4 + r) * PAD + tx + 16 * c] = s[r][c];
        __syncthreads();

        // ---- O += P @ K   (V == K; thread d cols tx*4+c) ----
        #pragma unroll
        for (int k4 = 0; k4 < 16; ++k4) {
            float4 pv[4], kv[4];
            #pragma unroll
            for (int r = 0; r < 4; ++r) pv[r] = *(float4*)&Ps[(ty * 4 + r) * PAD + k4 * 4];
            #pragma unroll
            for (int j = 0; j < 4; ++j) kv[j] = *(float4*)&Ks[(k4 * 4 + j) * PAD + tx * 4];
            #pragma unroll
            for (int r = 0; r < 4; ++r) {
                float p0 = pv[r].x, p1 = pv[r].y, p2 = pv[r].z, p3 = pv[r].w;
                acc[r][0] += p0 * kv[0].x + p1 * kv[1].x + p2 * kv[2].x + p3 * kv[3].x;
                acc[r][1] += p0 * kv[0].y + p1 * kv[1].y + p2 * kv[2].y + p3 * kv[3].y;
                acc[r][2] += p0 * kv[0].z + p1 * kv[1].z + p2 * kv[2].z + p3 * kv[3].z;
                acc[r][3] += p0 * kv[0].w + p1 * kv[1].w + p2 * kv[2].w + p3 * kv[3].w;
            }
        }
    }

    // epilogue: normalize, transpose through smem, coalesced store to out[bh][d][q]
    __syncthreads();
    #pragma unroll
    for (int r = 0; r < 4; ++r) {
        float inv = 1.0f / lrow[r];
        #pragma unroll
        for (int c = 0; c < 4; ++c)
            Qs[(tx * 4 + c) * PAD + ty * 4 + r] = acc[r][c] * inv;  // Os[d][q]
    }
    __syncthreads();
    float* obase = out + (size_t)bh * HD * NSEQ + q0;
    #pragma unroll
    for (int i = 0; i < 4; ++i) {
        int lin = tid + i * 256;
        int d = lin >> 4, c4 = (lin & 15) * 4;
        *(float4*)&obase[(size_t)d * NSEQ + c4] = *(float4*)&Qs[d * PAD + c4];
    }
}

// ---------------------------------------------------------------------------
extern "C" void kernel_launch(void* const* d_in, const int* in_sizes, int n_in,
                              void* d_out, int out_size) {
    const float* x  = (const float*)d_in[0];
    const float* Wq = (const float*)d_in[1];
    float* out = (float*)d_out;

    const int attn_smem = 3 * 64 * PAD * sizeof(float);  // 52224 > 48K static limit
    cudaFuncSetAttribute(attn_kernel, cudaFuncAttributeMaxDynamicSharedMemorySize,
                         attn_smem);

    qkv_gemm<<<dim3(64, 12), 256>>>(x, Wq);
    attn_kernel<<<dim3(32, 24), 256, attn_smem>>>(out);
}

// round 4
// speedup vs baseline: 2.6215x; 2.6215x over previous
#include <cuda_runtime.h>

#define NH   12
#define HD   64
#define NSEQ 2048
#define NB   2
#define DIN  768
#define PADA 68   // attention smem row stride (== 4 mod 32 -> conflict-free frags)
#define PADG 36   // gemm smem row stride
#define MASKV (-3e30f)   // must be well below MINIT so masked rows underflow to 0
#define MINIT (-1e30f)

// scratch: h = x @ Wq^T (pre-rounded to tf32), laid out [b][head][q][d]
__device__ float g_h[NB * NH * NSEQ * HD];

__device__ __forceinline__ unsigned f2tf(float f) {
    unsigned u; asm("cvt.rna.tf32.f32 %0, %1;" : "=r"(u) : "f"(f)); return u;
}
__device__ __forceinline__ void mma8(float d[4], const unsigned a[4], const unsigned b[2]) {
    asm volatile(
        "mma.sync.aligned.m16n8k8.row.col.f32.tf32.tf32.f32 "
        "{%0,%1,%2,%3},{%4,%5,%6,%7},{%8,%9},{%0,%1,%2,%3};"
        : "+f"(d[0]), "+f"(d[1]), "+f"(d[2]), "+f"(d[3])
        : "r"(a[0]), "r"(a[1]), "r"(a[2]), "r"(a[3]), "r"(b[0]), "r"(b[1]));
}

// ---------------------------------------------------------------------------
// Kernel 1: qkv projection  y[m][n] = sum_k x[m][k] * Wq[n][k]  via tf32 mma,
// scattered (tf32-rounded) into g_h[b][head][q][d].
// grid (32, 12): 128-row m tiles x one 64-col head. block 256 (8 warps 4x2).
// ---------------------------------------------------------------------------
__global__ __launch_bounds__(256) void qkv_gemm(const float* __restrict__ x,
                                                const float* __restrict__ Wq) {
    __shared__ unsigned As[128 * PADG];
    __shared__ unsigned Bs[64 * PADG];
    const int tid = threadIdx.x;
    const int lane = tid & 31, wid = tid >> 5;
    const int gid = lane >> 2, tig = lane & 3;
    const int wm = (wid & 3) * 32, wn = (wid >> 2) * 32;
    const int m0 = blockIdx.x * 128;
    const int head = blockIdx.y;
    const int n0 = head * 64;

    float acc[2][4][4] = {};

    for (int k0 = 0; k0 < DIN; k0 += 32) {
        #pragma unroll
        for (int i = 0; i < 4; ++i) {                 // A tile 128x32
            int idx = tid + i * 256;                  // float4 idx (1024)
            int row = idx >> 3, c4 = (idx & 7) * 4;
            float4 v = *(const float4*)&x[(size_t)(m0 + row) * DIN + k0 + c4];
            unsigned* d = &As[row * PADG + c4];
            d[0] = f2tf(v.x); d[1] = f2tf(v.y); d[2] = f2tf(v.z); d[3] = f2tf(v.w);
        }
        #pragma unroll
        for (int i = 0; i < 2; ++i) {                 // B tile 64x32
            int idx = tid + i * 256;                  // float4 idx (512)
            int row = idx >> 3, c4 = (idx & 7) * 4;
            float4 v = *(const float4*)&Wq[(size_t)(n0 + row) * DIN + k0 + c4];
            unsigned* d = &Bs[row * PADG + c4];
            d[0] = f2tf(v.x); d[1] = f2tf(v.y); d[2] = f2tf(v.z); d[3] = f2tf(v.w);
        }
        __syncthreads();
        #pragma unroll
        for (int k8 = 0; k8 < 4; ++k8) {
            unsigned a[2][4], b[4][2];
            #pragma unroll
            for (int mi = 0; mi < 2; ++mi) {
                int r = wm + mi * 16;
                a[mi][0] = As[(r + gid    ) * PADG + k8 * 8 + tig    ];
                a[mi][1] = As[(r + gid + 8) * PADG + k8 * 8 + tig    ];
                a[mi][2] = As[(r + gid    ) * PADG + k8 * 8 + tig + 4];
                a[mi][3] = As[(r + gid + 8) * PADG + k8 * 8 + tig + 4];
            }
            #pragma unroll
            for (int ni = 0; ni < 4; ++ni) {
                int c = wn + ni * 8;
                b[ni][0] = Bs[(c + gid) * PADG + k8 * 8 + tig    ];
                b[ni][1] = Bs[(c + gid) * PADG + k8 * 8 + tig + 4];
            }
            #pragma unroll
            for (int mi = 0; mi < 2; ++mi)
                #pragma unroll
                for (int ni = 0; ni < 4; ++ni)
                    mma8(acc[mi][ni], a[mi], b[ni]);
        }
        __syncthreads();
    }

    // epilogue: tf32-round and scatter to g_h[b][head][q][d]
    #pragma unroll
    for (int mi = 0; mi < 2; ++mi) {
        #pragma unroll
        for (int h = 0; h < 2; ++h) {
            int m = m0 + wm + mi * 16 + gid + h * 8;
            int b = m >> 11, q = m & 2047;
            float* dst = &g_h[((size_t)(b * NH + head) * NSEQ + q) * HD];
            #pragma unroll
            for (int ni = 0; ni < 4; ++ni) {
                int d = wn + ni * 8 + 2 * tig;
                float2 v;
                v.x = __uint_as_float(f2tf(acc[mi][ni][2 * h + 0]));
                v.y = __uint_as_float(f2tf(acc[mi][ni][2 * h + 1]));
                *(float2*)&dst[d] = v;
            }
        }
    }
}

// ---------------------------------------------------------------------------
// Kernel 2: fused causal flash attention (tf32 mma). K tile == V tile.
// grid (16 q-tiles of 128, 24 bh), block 256 (8 warps, 16 q-rows each).
// Output layout out[bh][d][q].
// ---------------------------------------------------------------------------
__global__ __launch_bounds__(256, 2) void attn_kernel(float* __restrict__ out) {
    extern __shared__ float smem[];
    float* Qs = smem;                      // 128*PADA
    float* Ks = smem + 128 * PADA;         // 64*PADA  (K and V)
    float* Ps = smem + 192 * PADA;         // 128*PADA

    const int tid = threadIdx.x;
    const int lane = tid & 31, wid = tid >> 5;
    const int gid = lane >> 2, tig = lane & 3;
    const int qt = 15 - blockIdx.x;        // heavy tiles scheduled first
    const int bh = blockIdx.y;
    const float* hbase = &g_h[(size_t)bh * NSEQ * HD];
    const int q0 = qt * 128;
    const int r0 = wid * 16;

    #pragma unroll
    for (int i = 0; i < 8; ++i) {          // Q tile 128x64
        int idx = tid + i * 256;           // float4 idx (2048)
        int row = idx >> 4, c4 = (idx & 15) * 4;
        *(float4*)&Qs[row * PADA + c4] =
            *(const float4*)&hbase[(size_t)(q0 + row) * HD + c4];
    }

    float o[8][4] = {};
    float mrow[2] = {MINIT, MINIT};
    float lrow[2] = {0.f, 0.f};

    const int nkt = 2 * qt + 2;
    for (int kt = 0; kt < nkt; ++kt) {
        __syncthreads();                   // Ks free (and Qs visible on iter 0)
        #pragma unroll
        for (int i = 0; i < 4; ++i) {      // K tile 64x64
            int idx = tid + i * 256;
            int row = idx >> 4, c4 = (idx & 15) * 4;
            *(float4*)&Ks[row * PADA + c4] =
                *(const float4*)&hbase[(size_t)(kt * 64 + row) * HD + c4];
        }
        __syncthreads();

        // ---- S = Q K^T ----
        float s[8][4] = {};
        #pragma unroll
        for (int k8 = 0; k8 < 8; ++k8) {
            unsigned a[4];
            a[0] = __float_as_uint(Qs[(r0 + gid    ) * PADA + k8 * 8 + tig    ]);
            a[1] = __float_as_uint(Qs[(r0 + gid + 8) * PADA + k8 * 8 + tig    ]);
            a[2] = __float_as_uint(Qs[(r0 + gid    ) * PADA + k8 * 8 + tig + 4]);
            a[3] = __float_as_uint(Qs[(r0 + gid + 8) * PADA + k8 * 8 + tig + 4]);
            #pragma unroll
            for (int ni = 0; ni < 8; ++ni) {
                unsigned b[2];
                b[0] = __float_as_uint(Ks[(ni * 8 + gid) * PADA + k8 * 8 + tig    ]);
                b[1] = __float_as_uint(Ks[(ni * 8 + gid) * PADA + k8 * 8 + tig + 4]);
                mma8(s[ni], a, b);
            }
        }

        // scale + causal mask (only last two kt tiles intersect the diagonal).
        // MASKV << MINIT so fully-masked rows give p = exp(MASKV-MINIT) = 0.
        const float sc = 0.125f;
        if (kt >= 2 * qt) {
            int qg0 = q0 + r0 + gid, qg1 = qg0 + 8;
            #pragma unroll
            for (int ni = 0; ni < 8; ++ni) {
                int kg = kt * 64 + ni * 8 + 2 * tig;
                s[ni][0] = (kg     > qg0) ? MASKV : s[ni][0] * sc;
                s[ni][1] = (kg + 1 > qg0) ? MASKV : s[ni][1] * sc;
                s[ni][2] = (kg     > qg1) ? MASKV : s[ni][2] * sc;
                s[ni][3] = (kg + 1 > qg1) ? MASKV : s[ni][3] * sc;
            }
        } else {
            #pragma unroll
            for (int ni = 0; ni < 8; ++ni)
                #pragma unroll
                for (int j = 0; j < 4; ++j) s[ni][j] *= sc;
        }

        // ---- online softmax (row h: regs 2h,2h+1; quad lanes share a row) ----
        #pragma unroll
        for (int h = 0; h < 2; ++h) {
            float mx = MASKV;
            #pragma unroll
            for (int ni = 0; ni < 8; ++ni)
                mx = fmaxf(mx, fmaxf(s[ni][2 * h], s[ni][2 * h + 1]));
            mx = fmaxf(mx, __shfl_xor_sync(0xffffffffu, mx, 1));
            mx = fmaxf(mx, __shfl_xor_sync(0xffffffffu, mx, 2));
            float mn = fmaxf(mrow[h], mx);          // >= MINIT always
            float corr = __expf(mrow[h] - mn);
            mrow[h] = mn;
            float rs = 0.f;
            #pragma unroll
            for (int ni = 0; ni < 8; ++ni) {
                float p0 = __expf(s[ni][2 * h    ] - mn);
                float p1 = __expf(s[ni][2 * h + 1] - mn);
                s[ni][2 * h] = p0; s[ni][2 * h + 1] = p1;
                rs += p0 + p1;
            }
            rs += __shfl_xor_sync(0xffffffffu, rs, 1);
            rs += __shfl_xor_sync(0xffffffffu, rs, 2);
            lrow[h] = lrow[h] * corr + rs;
            #pragma unroll
            for (int ni = 0; ni < 8; ++ni) { o[ni][2 * h] *= corr; o[ni][2 * h + 1] *= corr; }
        }

        // ---- stage P (warp-private rows -> only __syncwarp needed) ----
        #pragma unroll
        for (int ni = 0; ni < 8; ++ni) {
            int col = ni * 8 + 2 * tig;
            float2 v0, v1;
            v0.x = __uint_as_float(f2tf(s[ni][0])); v0.y = __uint_as_float(f2tf(s[ni][1]));
            v1.x = __uint_as_float(f2tf(s[ni][2])); v1.y = __uint_as_float(f2tf(s[ni][3]));
            *(float2*)&Ps[(r0 + gid    ) * PADA + col] = v0;
            *(float2*)&Ps[(r0 + gid + 8) * PADA + col] = v1;
        }
        __syncwarp();

        // ---- O += P @ V  (V == K) ----
        #pragma unroll
        for (int k8 = 0; k8 < 8; ++k8) {
            unsigned a[4];
            a[0] = __float_as_uint(Ps[(r0 + gid    ) * PADA + k8 * 8 + tig    ]);
            a[1] = __float_as_uint(Ps[(r0 + gid + 8) * PADA + k8 * 8 + tig    ]);
            a[2] = __float_as_uint(Ps[(r0 + gid    ) * PADA + k8 * 8 + tig + 4]);
            a[3] = __float_as_uint(Ps[(r0 + gid + 8) * PADA + k8 * 8 + tig + 4]);
            #pragma unroll
            for (int ni = 0; ni < 8; ++ni) {
                unsigned b[2];
                b[0] = __float_as_uint(Ks[(k8 * 8 + tig    ) * PADA + ni * 8 + gid]);
                b[1] = __float_as_uint(Ks[(k8 * 8 + tig + 4) * PADA + ni * 8 + gid]);
                mma8(o[ni], a, b);
            }
        }
    }

    // epilogue: normalize, transpose through smem, coalesced store out[bh][d][q]
    __syncthreads();
    float* Os = smem;                       // 64 x 132 staging
    float inv0 = 1.0f / lrow[0], inv1 = 1.0f / lrow[1];
    #pragma unroll
    for (int ni = 0; ni < 8; ++ni) {
        int d = ni * 8 + 2 * tig;
        Os[(d    ) * 132 + r0 + gid    ] = o[ni][0] * inv0;
        Os[(d + 1) * 132 + r0 + gid    ] = o[ni][1] * inv0;
        Os[(d    ) * 132 + r0 + gid + 8] = o[ni][2] * inv1;
        Os[(d + 1) * 132 + r0 + gid + 8] = o[ni][3] * inv1;
    }
    __syncthreads();
    float* obase = out + (size_t)bh * HD * NSEQ + q0;
    #pragma unroll
    for (int i = 0; i < 8; ++i) {           // FIX: 2048 float4s (was 512 -> 1/4 tile)
        int idx = tid + i * 256;
        int d = idx >> 5, q4 = (idx & 31) * 4;
        *(float4*)&obase[(size_t)d * NSEQ + q4] = *(float4*)&Os[d * 132 + q4];
    }
}

// ---------------------------------------------------------------------------
extern "C" void kernel_launch(void* const* d_in, const int* in_sizes, int n_in,
                              void* d_out, int out_size) {
    const float* x  = (const float*)d_in[0];
    const float* Wq = (const float*)d_in[1];
    float* out = (float*)d_out;

    const int attn_smem = 320 * PADA * sizeof(float);   // 87040 B
    cudaFuncSetAttribute(attn_kernel, cudaFuncAttributeMaxDynamicSharedMemorySize,
                         attn_smem);

    qkv_gemm<<<dim3(32, 12), 256>>>(x, Wq);
    attn_kernel<<<dim3(16, 24), 256, attn_smem>>>(out);
}

// round 5
// speedup vs baseline: 2.7396x; 1.0450x over previous
#include <cuda_runtime.h>

#define NH   12
#define HD   64
#define NSEQ 2048
#define NB   2
#define DIN  768
#define PADA 68   // attention smem row stride (== 4 mod 32 -> conflict-free frags)
#define PADG 36   // gemm smem row stride
#define MASKV (-3e30f)   // must be well below MINIT so masked rows underflow to 0
#define MINIT (-1e30f)

// scratch: h = x @ Wq^T (pre-rounded to tf32), laid out [b][head][q][d]
__device__ float g_h[NB * NH * NSEQ * HD];

__device__ __forceinline__ unsigned f2tf(float f) {
    unsigned u; asm("cvt.rna.tf32.f32 %0, %1;" : "=r"(u) : "f"(f)); return u;
}
__device__ __forceinline__ void mma8(float d[4], const unsigned a[4], const unsigned b[2]) {
    asm volatile(
        "mma.sync.aligned.m16n8k8.row.col.f32.tf32.tf32.f32 "
        "{%0,%1,%2,%3},{%4,%5,%6,%7},{%8,%9},{%0,%1,%2,%3};"
        : "+f"(d[0]), "+f"(d[1]), "+f"(d[2]), "+f"(d[3])
        : "r"(a[0]), "r"(a[1]), "r"(a[2]), "r"(a[3]), "r"(b[0]), "r"(b[1]));
}

// ---------------------------------------------------------------------------
// Kernel 1: qkv projection  y[m][n] = sum_k x[m][k] * Wq[n][k]  via tf32 mma,
// scattered (tf32-rounded) into g_h[b][head][q][d].
// grid (32, 12): 128-row m tiles x one 64-col head. block 256 (8 warps 4x2).
// ---------------------------------------------------------------------------
__global__ __launch_bounds__(256) void qkv_gemm(const float* __restrict__ x,
                                                const float* __restrict__ Wq) {
    __shared__ unsigned As[128 * PADG];
    __shared__ unsigned Bs[64 * PADG];
    const int tid = threadIdx.x;
    const int lane = tid & 31, wid = tid >> 5;
    const int gid = lane >> 2, tig = lane & 3;
    const int wm = (wid & 3) * 32, wn = (wid >> 2) * 32;
    const int m0 = blockIdx.x * 128;
    const int head = blockIdx.y;
    const int n0 = head * 64;

    float acc[2][4][4] = {};

    for (int k0 = 0; k0 < DIN; k0 += 32) {
        #pragma unroll
        for (int i = 0; i < 4; ++i) {                 // A tile 128x32
            int idx = tid + i * 256;                  // float4 idx (1024)
            int row = idx >> 3, c4 = (idx & 7) * 4;
            float4 v = *(const float4*)&x[(size_t)(m0 + row) * DIN + k0 + c4];
            unsigned* d = &As[row * PADG + c4];
            d[0] = f2tf(v.x); d[1] = f2tf(v.y); d[2] = f2tf(v.z); d[3] = f2tf(v.w);
        }
        #pragma unroll
        for (int i = 0; i < 2; ++i) {                 // B tile 64x32
            int idx = tid + i * 256;                  // float4 idx (512)
            int row = idx >> 3, c4 = (idx & 7) * 4;
            float4 v = *(const float4*)&Wq[(size_t)(n0 + row) * DIN + k0 + c4];
            unsigned* d = &Bs[row * PADG + c4];
            d[0] = f2tf(v.x); d[1] = f2tf(v.y); d[2] = f2tf(v.z); d[3] = f2tf(v.w);
        }
        __syncthreads();
        #pragma unroll
        for (int k8 = 0; k8 < 4; ++k8) {
            unsigned a[2][4], b[4][2];
            #pragma unroll
            for (int mi = 0; mi < 2; ++mi) {
                int r = wm + mi * 16;
                a[mi][0] = As[(r + gid    ) * PADG + k8 * 8 + tig    ];
                a[mi][1] = As[(r + gid + 8) * PADG + k8 * 8 + tig    ];
                a[mi][2] = As[(r + gid    ) * PADG + k8 * 8 + tig + 4];
                a[mi][3] = As[(r + gid + 8) * PADG + k8 * 8 + tig + 4];
            }
            #pragma unroll
            for (int ni = 0; ni < 4; ++ni) {
                int c = wn + ni * 8;
                b[ni][0] = Bs[(c + gid) * PADG + k8 * 8 + tig    ];
                b[ni][1] = Bs[(c + gid) * PADG + k8 * 8 + tig + 4];
            }
            #pragma unroll
            for (int mi = 0; mi < 2; ++mi)
                #pragma unroll
                for (int ni = 0; ni < 4; ++ni)
                    mma8(acc[mi][ni], a[mi], b[ni]);
        }
        __syncthreads();
    }

    // epilogue: tf32-round and scatter to g_h[b][head][q][d]
    #pragma unroll
    for (int mi = 0; mi < 2; ++mi) {
        #pragma unroll
        for (int h = 0; h < 2; ++h) {
            int m = m0 + wm + mi * 16 + gid + h * 8;
            int b = m >> 11, q = m & 2047;
            float* dst = &g_h[((size_t)(b * NH + head) * NSEQ + q) * HD];
            #pragma unroll
            for (int ni = 0; ni < 4; ++ni) {
                int d = wn + ni * 8 + 2 * tig;
                float2 v;
                v.x = __uint_as_float(f2tf(acc[mi][ni][2 * h + 0]));
                v.y = __uint_as_float(f2tf(acc[mi][ni][2 * h + 1]));
                *(float2*)&dst[d] = v;
            }
        }
    }
}

// ---------------------------------------------------------------------------
// Kernel 2: fused causal flash attention (tf32 mma). K tile == V tile.
// Double-buffered cp.async K pipeline, ONE barrier per k-tile.
// grid (16 q-tiles of 128, 24 bh), block 256 (8 warps, 16 q-rows each).
// Output layout out[bh][d][q].
// ---------------------------------------------------------------------------
__device__ __forceinline__ void load_ktile_async(float* kbuf, const float* src,
                                                 int tid) {
    #pragma unroll
    for (int i = 0; i < 4; ++i) {
        int idx = tid + i * 256;                   // float4 idx (1024)
        int row = idx >> 4, c4 = (idx & 15) * 4;
        unsigned dst = (unsigned)__cvta_generic_to_shared(&kbuf[row * PADA + c4]);
        asm volatile("cp.async.cg.shared.global [%0], [%1], 16;"
                     :: "r"(dst), "l"(src + (size_t)row * HD + c4));
    }
    asm volatile("cp.async.commit_group;");
}

__global__ __launch_bounds__(256, 2) void attn_kernel(float* __restrict__ out) {
    extern __shared__ float smem[];
    float* Qs  = smem;                      // 128*PADA
    float* Kb0 = smem + 128 * PADA;         // 64*PADA
    float* Kb1 = smem + 192 * PADA;         // 64*PADA
    float* Ps  = smem + 256 * PADA;         // 128*PADA

    const int tid = threadIdx.x;
    const int lane = tid & 31, wid = tid >> 5;
    const int gid = lane >> 2, tig = lane & 3;
    const int qt = 15 - blockIdx.x;         // heavy tiles scheduled first
    const int bh = blockIdx.y;
    const float* hbase = &g_h[(size_t)bh * NSEQ * HD];
    const int q0 = qt * 128;
    const int r0 = wid * 16;
    const int nkt = 2 * qt + 2;

    // prologue: async-load K tile 0, then regular-load Q tile
    load_ktile_async(Kb0, hbase, tid);
    #pragma unroll
    for (int i = 0; i < 8; ++i) {           // Q tile 128x64
        int idx = tid + i * 256;            // float4 idx (2048)
        int row = idx >> 4, c4 = (idx & 15) * 4;
        *(float4*)&Qs[row * PADA + c4] =
            *(const float4*)&hbase[(size_t)(q0 + row) * HD + c4];
    }

    float o[8][4] = {};
    float mrow[2] = {MINIT, MINIT};
    float lrow[2] = {0.f, 0.f};

    // base-2 softmax: scale = (1/sqrt(64)) * log2(e)
    const float sc2 = 0.18033688011112042f;

    for (int kt = 0; kt < nkt; ++kt) {
        // tile kt arrived (my copies)...
        asm volatile("cp.async.wait_group 0;");
        // ...all copies visible AND all warps done reading buf[(kt+1)&1] (iter kt-1)
        __syncthreads();
        if (kt + 1 < nkt)
            load_ktile_async(((kt + 1) & 1) ? Kb1 : Kb0,
                             hbase + (size_t)(kt + 1) * 64 * HD, tid);
        float* Ks = (kt & 1) ? Kb1 : Kb0;

        // ---- S = Q K^T ----
        float s[8][4] = {};
        #pragma unroll
        for (int k8 = 0; k8 < 8; ++k8) {
            unsigned a[4];
            a[0] = __float_as_uint(Qs[(r0 + gid    ) * PADA + k8 * 8 + tig    ]);
            a[1] = __float_as_uint(Qs[(r0 + gid + 8) * PADA + k8 * 8 + tig    ]);
            a[2] = __float_as_uint(Qs[(r0 + gid    ) * PADA + k8 * 8 + tig + 4]);
            a[3] = __float_as_uint(Qs[(r0 + gid + 8) * PADA + k8 * 8 + tig + 4]);
            #pragma unroll
            for (int ni = 0; ni < 8; ++ni) {
                unsigned b[2];
                b[0] = __float_as_uint(Ks[(ni * 8 + gid) * PADA + k8 * 8 + tig    ]);
                b[1] = __float_as_uint(Ks[(ni * 8 + gid) * PADA + k8 * 8 + tig + 4]);
                mma8(s[ni], a, b);
            }
        }

        // scale (base-2) + causal mask. MASKV << MINIT so fully-masked rows
        // give p = exp2(MASKV-MINIT) = 0, never exp2(0)=1.
        if (kt >= 2 * qt) {
            int qg0 = q0 + r0 + gid, qg1 = qg0 + 8;
            #pragma unroll
            for (int ni = 0; ni < 8; ++ni) {
                int kg = kt * 64 + ni * 8 + 2 * tig;
                s[ni][0] = (kg     > qg0) ? MASKV : s[ni][0] * sc2;
                s[ni][1] = (kg + 1 > qg0) ? MASKV : s[ni][1] * sc2;
                s[ni][2] = (kg     > qg1) ? MASKV : s[ni][2] * sc2;
                s[ni][3] = (kg + 1 > qg1) ? MASKV : s[ni][3] * sc2;
            }
        } else {
            #pragma unroll
            for (int ni = 0; ni < 8; ++ni)
                #pragma unroll
                for (int j = 0; j < 4; ++j) s[ni][j] *= sc2;
        }

        // ---- online softmax in base 2 (row h: regs 2h,2h+1; quads share rows) ----
        #pragma unroll
        for (int h = 0; h < 2; ++h) {
            float mx = MASKV;
            #pragma unroll
            for (int ni = 0; ni < 8; ++ni)
                mx = fmaxf(mx, fmaxf(s[ni][2 * h], s[ni][2 * h + 1]));
            mx = fmaxf(mx, __shfl_xor_sync(0xffffffffu, mx, 1));
            mx = fmaxf(mx, __shfl_xor_sync(0xffffffffu, mx, 2));
            float mn = fmaxf(mrow[h], mx);          // >= MINIT always
            float corr = exp2f(mrow[h] - mn);
            mrow[h] = mn;
            float rs = 0.f;
            #pragma unroll
            for (int ni = 0; ni < 8; ++ni) {
                float p0 = exp2f(s[ni][2 * h    ] - mn);
                float p1 = exp2f(s[ni][2 * h + 1] - mn);
                s[ni][2 * h] = p0; s[ni][2 * h + 1] = p1;
                rs += p0 + p1;
            }
            rs += __shfl_xor_sync(0xffffffffu, rs, 1);
            rs += __shfl_xor_sync(0xffffffffu, rs, 2);
            lrow[h] = lrow[h] * corr + rs;
            #pragma unroll
            for (int ni = 0; ni < 8; ++ni) { o[ni][2 * h] *= corr; o[ni][2 * h + 1] *= corr; }
        }

        // ---- stage P (warp-private rows -> only __syncwarp needed) ----
        #pragma unroll
        for (int ni = 0; ni < 8; ++ni) {
            int col = ni * 8 + 2 * tig;
            float2 v0, v1;
            v0.x = __uint_as_float(f2tf(s[ni][0])); v0.y = __uint_as_float(f2tf(s[ni][1]));
            v1.x = __uint_as_float(f2tf(s[ni][2])); v1.y = __uint_as_float(f2tf(s[ni][3]));
            *(float2*)&Ps[(r0 + gid    ) * PADA + col] = v0;
            *(float2*)&Ps[(r0 + gid + 8) * PADA + col] = v1;
        }
        __syncwarp();

        // ---- O += P @ V  (V == K) ----
        #pragma unroll
        for (int k8 = 0; k8 < 8; ++k8) {
            unsigned a[4];
            a[0] = __float_as_uint(Ps[(r0 + gid    ) * PADA + k8 * 8 + tig    ]);
            a[1] = __float_as_uint(Ps[(r0 + gid + 8) * PADA + k8 * 8 + tig    ]);
            a[2] = __float_as_uint(Ps[(r0 + gid    ) * PADA + k8 * 8 + tig + 4]);
            a[3] = __float_as_uint(Ps[(r0 + gid + 8) * PADA + k8 * 8 + tig + 4]);
            #pragma unroll
            for (int ni = 0; ni < 8; ++ni) {
                unsigned b[2];
                b[0] = __float_as_uint(Ks[(k8 * 8 + tig    ) * PADA + ni * 8 + gid]);
                b[1] = __float_as_uint(Ks[(k8 * 8 + tig + 4) * PADA + ni * 8 + gid]);
                mma8(o[ni], a, b);
            }
        }
    }

    // epilogue: normalize, transpose through smem, coalesced store out[bh][d][q]
    __syncthreads();
    float* Os = smem;                       // 64 x 132 staging
    float inv0 = 1.0f / lrow[0], inv1 = 1.0f / lrow[1];
    #pragma unroll
    for (int ni = 0; ni < 8; ++ni) {
        int d = ni * 8 + 2 * tig;
        Os[(d    ) * 132 + r0 + gid    ] = o[ni][0] * inv0;
        Os[(d + 1) * 132 + r0 + gid    ] = o[ni][1] * inv0;
        Os[(d    ) * 132 + r0 + gid + 8] = o[ni][2] * inv1;
        Os[(d + 1) * 132 + r0 + gid + 8] = o[ni][3] * inv1;
    }
    __syncthreads();
    float* obase = out + (size_t)bh * HD * NSEQ + q0;
    #pragma unroll
    for (int i = 0; i < 8; ++i) {           // 2048 float4s = full 64x128 tile
        int idx = tid + i * 256;
        int d = idx >> 5, q4 = (idx & 31) * 4;
        *(float4*)&obase[(size_t)d * NSEQ + q4] = *(float4*)&Os[d * 132 + q4];
    }
}

// ---------------------------------------------------------------------------
extern "C" void kernel_launch(void* const* d_in, const int* in_sizes, int n_in,
                              void* d_out, int out_size) {
    const float* x  = (const float*)d_in[0];
    const float* Wq = (const float*)d_in[1];
    float* out = (float*)d_out;

    const int attn_smem = 384 * PADA * sizeof(float);   // 104448 B
    cudaFuncSetAttribute(attn_kernel, cudaFuncAttributeMaxDynamicSharedMemorySize,
                         attn_smem);

    qkv_gemm<<<dim3(32, 12), 256>>>(x, Wq);
    attn_kernel<<<dim3(16, 24), 256, attn_smem>>>(out);
}